// round 1
// baseline (speedup 1.0000x reference)
#include <cuda_runtime.h>
#include <cuda_bf16.h>

// Problem constants (fixed shapes from reference):
//   pred_logits   [16,32,1024,80] f32  -- UNUSED by the math
//   pred_logits_b [16,32,1024,2]  f32
//   pred_boxes    [16,32,1024,4]  f32
//   tgt_bbox      [16,32,1,4]     f32
//   tgt_ids       [512]           i64  -- UNUSED
// Output (concatenated, f32): C [512*1024], rows [512], mode_idx [1]

#define NBS 16
#define NT  32
#define NQ  1024
#define NF  (NBS * NT)        // 512 frames
#define C_SIZE (NF * NQ)      // 524288

__device__ int g_rows[NF];    // scratch: argmin index per frame (int form)

__global__ void __launch_bounds__(256, 8)
cost_argmin_kernel(const float* __restrict__ logits_b,
                   const float* __restrict__ boxes,
                   const float* __restrict__ tgt,
                   float* __restrict__ out)
{
    const int f   = blockIdx.x;   // frame index 0..511
    const int tid = threadIdx.x;  // 0..255

    // Target box for this frame (cxcywh -> xyxy)
    const float4 tb = reinterpret_cast<const float4*>(tgt)[f];
    const float tx1 = tb.x - 0.5f * tb.z;
    const float ty1 = tb.y - 0.5f * tb.w;
    const float tx2 = tb.x + 0.5f * tb.z;
    const float ty2 = tb.y + 0.5f * tb.w;
    const float area2 = (tx2 - tx1) * (ty2 - ty1);

    const float4* __restrict__ bptr = reinterpret_cast<const float4*>(boxes)    + (size_t)f * NQ;
    const float2* __restrict__ lptr = reinterpret_cast<const float2*>(logits_b) + (size_t)f * NQ;
    float* __restrict__ cptr = out + (size_t)f * NQ;

    float best  = 3.402823466e+38f;
    int   bestq = 0;

    #pragma unroll
    for (int k = 0; k < NQ; k += 256) {
        const int q = k + tid;
        const float4 p = bptr[q];   // cx, cy, w, h
        const float2 l = lptr[q];

        // L1 cost in cxcywh space
        const float cost_bbox = fabsf(p.x - tb.x) + fabsf(p.y - tb.y)
                              + fabsf(p.z - tb.z) + fabsf(p.w - tb.w);

        // xyxy conversion (matches reference arithmetic)
        const float x1 = p.x - 0.5f * p.z;
        const float y1 = p.y - 0.5f * p.w;
        const float x2 = p.x + 0.5f * p.z;
        const float y2 = p.y + 0.5f * p.w;
        const float area1 = (x2 - x1) * (y2 - y1);

        // intersection
        const float lt_x = fmaxf(x1, tx1), lt_y = fmaxf(y1, ty1);
        const float rb_x = fminf(x2, tx2), rb_y = fminf(y2, ty2);
        const float iw = fmaxf(rb_x - lt_x, 0.0f);
        const float ih = fmaxf(rb_y - lt_y, 0.0f);
        const float inter = iw * ih;
        const float uni   = area1 + area2 - inter;
        const float iou   = inter / uni;

        // enclosing box
        const float cx1 = fminf(x1, tx1), cy1 = fminf(y1, ty1);
        const float cx2 = fmaxf(x2, tx2), cy2 = fmaxf(y2, ty2);
        const float cw = fmaxf(cx2 - cx1, 0.0f);
        const float ch = fmaxf(cy2 - cy1, 0.0f);
        const float areac = cw * ch;
        const float giou  = iou - (areac - uni) / areac;

        // -softmax(l)[1] == -sigmoid(l1 - l0)
        const float cost_class = -1.0f / (1.0f + expf(l.x - l.y));

        const float c = 5.0f * cost_bbox + cost_class + 2.0f * (-giou);
        cptr[q] = c;

        // first-min tie-break: within a thread q is strictly increasing, so '<' is enough
        if (c < best) { best = c; bestq = q; }
    }

    // Block argmin reduce (value min; on exact tie, smaller index wins)
    __shared__ float sv[256];
    __shared__ int   si[256];
    sv[tid] = best; si[tid] = bestq;
    __syncthreads();
    #pragma unroll
    for (int s = 128; s > 0; s >>= 1) {
        if (tid < s) {
            const float v2 = sv[tid + s];
            const int   i2 = si[tid + s];
            if (v2 < sv[tid] || (v2 == sv[tid] && i2 < si[tid])) {
                sv[tid] = v2; si[tid] = i2;
            }
        }
        __syncthreads();
    }
    if (tid == 0) {
        g_rows[f] = si[0];
        out[C_SIZE + f] = (float)si[0];   // rows output
    }
}

// Single block, 1024 threads: bincount of g_rows (512 entries) into 1024 bins,
// then argmax with smallest-index tie-break (JAX argmax semantics).
__global__ void __launch_bounds__(1024, 1)
mode_kernel(float* __restrict__ out)
{
    __shared__ int cnt[NQ];
    __shared__ int key[NQ];
    const int tid = threadIdx.x;

    cnt[tid] = 0;
    __syncthreads();
    if (tid < NF) atomicAdd(&cnt[g_rows[tid]], 1);
    __syncthreads();

    // key = (count << 10) | (1023 - idx): max over keys => max count, then min idx
    key[tid] = (cnt[tid] << 10) | (NQ - 1 - tid);
    __syncthreads();
    #pragma unroll
    for (int s = 512; s > 0; s >>= 1) {
        if (tid < s) {
            const int k2 = key[tid + s];
            if (k2 > key[tid]) key[tid] = k2;
        }
        __syncthreads();
    }
    if (tid == 0) {
        const int mode_idx = (NQ - 1) - (key[0] & (NQ - 1));
        out[C_SIZE + NF] = (float)mode_idx;
    }
}

extern "C" void kernel_launch(void* const* d_in, const int* in_sizes, int n_in,
                              void* d_out, int out_size)
{
    // metadata order: pred_logits, pred_logits_b, pred_boxes, tgt_bbox, tgt_ids
    const float* logits_b = (const float*)d_in[1];
    const float* boxes    = (const float*)d_in[2];
    const float* tgt      = (const float*)d_in[3];
    float* out = (float*)d_out;

    cost_argmin_kernel<<<NF, 256>>>(logits_b, boxes, tgt, out);
    mode_kernel<<<1, 1024>>>(out);
}

// round 2
// speedup vs baseline: 1.0221x; 1.0221x over previous
#include <cuda_runtime.h>
#include <cuda_bf16.h>

// Problem constants (fixed shapes from reference):
//   pred_logits   [16,32,1024,80] f32  -- UNUSED by the math
//   pred_logits_b [16,32,1024,2]  f32
//   pred_boxes    [16,32,1024,4]  f32
//   tgt_bbox      [16,32,1,4]     f32
//   tgt_ids       [512]           i64  -- UNUSED
// Output (concatenated, f32): C [512*1024], rows [512], mode_idx [1]

#define NBS 16
#define NT  32
#define NQ  1024
#define NF  (NBS * NT)        // 512 frames
#define C_SIZE (NF * NQ)      // 524288

__device__ int          g_rows[NF];   // argmin index per frame
__device__ unsigned int g_done;       // zero-initialized completion counter

// Monotone float -> uint mapping: a < b  <=>  enc(a) < enc(b)
__device__ __forceinline__ unsigned int float_to_ordered(float f) {
    unsigned int u = __float_as_uint(f);
    return (u & 0x80000000u) ? ~u : (u | 0x80000000u);
}

__global__ void __launch_bounds__(256, 8)
fused_kernel(const float* __restrict__ logits_b,
             const float* __restrict__ boxes,
             const float* __restrict__ tgt,
             float* __restrict__ out)
{
    const int f    = blockIdx.x;   // frame 0..511
    const int tid  = threadIdx.x;  // 0..255
    const int lane = tid & 31;
    const int wid  = tid >> 5;

    // Target box (cxcywh -> xyxy)
    const float4 tb = reinterpret_cast<const float4*>(tgt)[f];
    const float tx1 = tb.x - 0.5f * tb.z;
    const float ty1 = tb.y - 0.5f * tb.w;
    const float tx2 = tb.x + 0.5f * tb.z;
    const float ty2 = tb.y + 0.5f * tb.w;
    const float area2 = (tx2 - tx1) * (ty2 - ty1);

    const float4* __restrict__ bptr = reinterpret_cast<const float4*>(boxes)    + (size_t)f * NQ;
    const float2* __restrict__ lptr = reinterpret_cast<const float2*>(logits_b) + (size_t)f * NQ;
    float* __restrict__ cptr = out + (size_t)f * NQ;

    // Hoist all loads up front: 8 independent loads in flight (MLP=8)
    float4 p[4];
    float2 l[4];
    #pragma unroll
    for (int i = 0; i < 4; i++) {
        p[i] = bptr[i * 256 + tid];
        l[i] = lptr[i * 256 + tid];
    }

    unsigned long long bestkey = 0xFFFFFFFFFFFFFFFFull;

    #pragma unroll
    for (int i = 0; i < 4; i++) {
        const int q = i * 256 + tid;

        // L1 cost in cxcywh space
        const float cost_bbox = fabsf(p[i].x - tb.x) + fabsf(p[i].y - tb.y)
                              + fabsf(p[i].z - tb.z) + fabsf(p[i].w - tb.w);

        // xyxy
        const float x1 = p[i].x - 0.5f * p[i].z;
        const float y1 = p[i].y - 0.5f * p[i].w;
        const float x2 = p[i].x + 0.5f * p[i].z;
        const float y2 = p[i].y + 0.5f * p[i].w;
        const float area1 = (x2 - x1) * (y2 - y1);

        // intersection / union / iou
        const float lt_x = fmaxf(x1, tx1), lt_y = fmaxf(y1, ty1);
        const float rb_x = fminf(x2, tx2), rb_y = fminf(y2, ty2);
        const float iw = fmaxf(rb_x - lt_x, 0.0f);
        const float ih = fmaxf(rb_y - lt_y, 0.0f);
        const float inter = iw * ih;
        const float uni   = area1 + area2 - inter;
        const float iou   = inter / uni;

        // enclosing box
        const float cx1 = fminf(x1, tx1), cy1 = fminf(y1, ty1);
        const float cx2 = fmaxf(x2, tx2), cy2 = fmaxf(y2, ty2);
        const float cw = fmaxf(cx2 - cx1, 0.0f);
        const float ch = fmaxf(cy2 - cy1, 0.0f);
        const float areac = cw * ch;
        const float giou  = iou - (areac - uni) / areac;

        // -softmax(l)[1] == -sigmoid(l1 - l0)
        const float cost_class = -1.0f / (1.0f + expf(l[i].x - l[i].y));

        const float c = 5.0f * cost_bbox + cost_class - 2.0f * giou;
        cptr[q] = c;

        // packed key: smaller cost wins; on exact tie, smaller q wins
        const unsigned long long key =
            ((unsigned long long)float_to_ordered(c) << 32) | (unsigned int)q;
        if (key < bestkey) bestkey = key;
    }

    // Warp-level min reduce of packed keys
    #pragma unroll
    for (int s = 16; s > 0; s >>= 1) {
        unsigned long long other = __shfl_down_sync(0xFFFFFFFFu, bestkey, s);
        if (other < bestkey) bestkey = other;
    }

    __shared__ unsigned long long warp_min[8];
    __shared__ int s_last;
    if (lane == 0) warp_min[wid] = bestkey;
    __syncthreads();

    if (tid == 0) {
        unsigned long long m = warp_min[0];
        #pragma unroll
        for (int w = 1; w < 8; w++)
            if (warp_min[w] < m) m = warp_min[w];
        const int q = (int)(m & 0xFFFFFFFFu);
        g_rows[f] = q;
        out[C_SIZE + f] = (float)q;

        // Signal completion (release: fence then relaxed atomic)
        __threadfence();
        const unsigned int v = atomicAdd(&g_done, 1u);
        s_last = (v == NF - 1) ? 1 : 0;
    }
    __syncthreads();

    // ---- Last block computes the mode over g_rows ----
    if (s_last) {
        __threadfence();  // acquire side of the counter handshake

        __shared__ int cnt[NQ];
        #pragma unroll
        for (int i = 0; i < 4; i++) cnt[i * 256 + tid] = 0;
        __syncthreads();

        #pragma unroll
        for (int i = 0; i < 2; i++) {
            const int r = *((volatile int*)&g_rows[i * 256 + tid]);
            atomicAdd(&cnt[r], 1);
        }
        __syncthreads();

        // key = (count << 10) | (1023 - idx): max => max count, then min idx
        int mykey = 0;
        #pragma unroll
        for (int i = 0; i < 4; i++) {
            const int bin = i * 256 + tid;
            const int k = (cnt[bin] << 10) | (NQ - 1 - bin);
            if (k > mykey) mykey = k;
        }
        #pragma unroll
        for (int s = 16; s > 0; s >>= 1) {
            const int other = __shfl_down_sync(0xFFFFFFFFu, mykey, s);
            if (other > mykey) mykey = other;
        }
        __shared__ int warp_max[8];
        if (lane == 0) warp_max[wid] = mykey;
        __syncthreads();
        if (tid == 0) {
            int m = warp_max[0];
            #pragma unroll
            for (int w = 1; w < 8; w++)
                if (warp_max[w] > m) m = warp_max[w];
            const int mode_idx = (NQ - 1) - (m & (NQ - 1));
            out[C_SIZE + NF] = (float)mode_idx;
            g_done = 0;   // reset for next graph replay
        }
    }
}

extern "C" void kernel_launch(void* const* d_in, const int* in_sizes, int n_in,
                              void* d_out, int out_size)
{
    // metadata order: pred_logits, pred_logits_b, pred_boxes, tgt_bbox, tgt_ids
    const float* logits_b = (const float*)d_in[1];
    const float* boxes    = (const float*)d_in[2];
    const float* tgt      = (const float*)d_in[3];
    float* out = (float*)d_out;

    fused_kernel<<<NF, 256>>>(logits_b, boxes, tgt, out);
}

// round 3
// speedup vs baseline: 1.2128x; 1.1866x over previous
#include <cuda_runtime.h>
#include <cuda_bf16.h>

// Problem constants (fixed shapes from reference):
//   pred_logits   [16,32,1024,80] f32  -- UNUSED by the math
//   pred_logits_b [16,32,1024,2]  f32
//   pred_boxes    [16,32,1024,4]  f32
//   tgt_bbox      [16,32,1,4]     f32
//   tgt_ids       [512]           i64  -- UNUSED
// Output (concatenated, f32): C [512*1024], rows [512], mode_idx [1]

#define NQ  1024
#define NF  512
#define C_SIZE (NF * NQ)      // 524288
#define TPB 512               // threads per block; 2 queries per thread

__device__ int          g_rows[NF];   // argmin index per frame
__device__ unsigned int g_done;       // zero-initialized completion counter

// Monotone float -> uint mapping: a < b  <=>  enc(a) < enc(b)
__device__ __forceinline__ unsigned int float_to_ordered(float f) {
    unsigned int u = __float_as_uint(f);
    return (u & 0x80000000u) ? ~u : (u | 0x80000000u);
}

__global__ void __launch_bounds__(TPB, 2)
fused_kernel(const float* __restrict__ logits_b,
             const float* __restrict__ boxes,
             const float* __restrict__ tgt,
             float* __restrict__ out)
{
    const int f    = blockIdx.x;   // frame 0..511
    const int tid  = threadIdx.x;  // 0..511
    const int lane = tid & 31;
    const int wid  = tid >> 5;     // 0..15

    // Target box (cxcywh -> xyxy)
    const float4 tb = reinterpret_cast<const float4*>(tgt)[f];
    const float tx1 = tb.x - 0.5f * tb.z;
    const float ty1 = tb.y - 0.5f * tb.w;
    const float tx2 = tb.x + 0.5f * tb.z;
    const float ty2 = tb.y + 0.5f * tb.w;
    const float area2 = (tx2 - tx1) * (ty2 - ty1);

    const float4* __restrict__ bptr = reinterpret_cast<const float4*>(boxes)    + (size_t)f * NQ;
    const float2* __restrict__ lptr = reinterpret_cast<const float2*>(logits_b) + (size_t)f * NQ;
    float* __restrict__ cptr = out + (size_t)f * NQ;

    // Front-batch all loads (MLP = 4 independent loads)
    float4 p[2];
    float2 l[2];
    #pragma unroll
    for (int i = 0; i < 2; i++) {
        p[i] = bptr[i * TPB + tid];
        l[i] = lptr[i * TPB + tid];
    }

    unsigned int obest = 0xFFFFFFFFu;  // ordered-encoded best cost
    int          bestq = 0;

    #pragma unroll
    for (int i = 0; i < 2; i++) {
        const int q = i * TPB + tid;

        // L1 cost in cxcywh space
        const float cost_bbox = fabsf(p[i].x - tb.x) + fabsf(p[i].y - tb.y)
                              + fabsf(p[i].z - tb.z) + fabsf(p[i].w - tb.w);

        // xyxy
        const float x1 = p[i].x - 0.5f * p[i].z;
        const float y1 = p[i].y - 0.5f * p[i].w;
        const float x2 = p[i].x + 0.5f * p[i].z;
        const float y2 = p[i].y + 0.5f * p[i].w;
        const float area1 = (x2 - x1) * (y2 - y1);

        // intersection / union / iou
        const float lt_x = fmaxf(x1, tx1), lt_y = fmaxf(y1, ty1);
        const float rb_x = fminf(x2, tx2), rb_y = fminf(y2, ty2);
        const float iw = fmaxf(rb_x - lt_x, 0.0f);
        const float ih = fmaxf(rb_y - lt_y, 0.0f);
        const float inter = iw * ih;
        const float uni   = area1 + area2 - inter;
        const float iou   = inter / uni;

        // enclosing box
        const float cx1 = fminf(x1, tx1), cy1 = fminf(y1, ty1);
        const float cx2 = fmaxf(x2, tx2), cy2 = fmaxf(y2, ty2);
        const float cw = fmaxf(cx2 - cx1, 0.0f);
        const float ch = fmaxf(cy2 - cy1, 0.0f);
        const float areac = cw * ch;
        const float giou  = iou - (areac - uni) / areac;

        // -softmax(l)[1] == -sigmoid(l1 - l0)
        const float cost_class = -1.0f / (1.0f + expf(l[i].x - l[i].y));

        const float c = 5.0f * cost_bbox + cost_class - 2.0f * giou;
        cptr[q] = c;

        const unsigned int oc = float_to_ordered(c);
        // per-thread: chunk order means q strictly increases -> '<' keeps first min
        if (oc < obest) { obest = oc; bestq = q; }
    }

    // Warp argmin: min cost, then min q among cost-ties (exact JAX tie-break)
    const unsigned int wmin = __reduce_min_sync(0xFFFFFFFFu, obest);
    const unsigned int qc   = (obest == wmin) ? (unsigned int)bestq : 0xFFFFFFFFu;
    const unsigned int wq   = __reduce_min_sync(0xFFFFFFFFu, qc);

    __shared__ unsigned long long warp_min[TPB / 32];
    __shared__ int s_last;
    if (lane == 0)
        warp_min[wid] = ((unsigned long long)wmin << 32) | wq;
    __syncthreads();

    if (tid == 0) {
        unsigned long long m = warp_min[0];
        #pragma unroll
        for (int w = 1; w < TPB / 32; w++)
            if (warp_min[w] < m) m = warp_min[w];
        const int q = (int)(m & 0xFFFFFFFFu);
        out[C_SIZE + f] = (float)q;   // rows output (read by host after kernel end)

        // Publish g_rows[f] with a strong relaxed store (goes to L2),
        // then release-increment the counter: orders ONLY this 4B store,
        // no CTA-wide STG drain, no L1 flush.
        asm volatile("st.relaxed.gpu.global.u32 [%0], %1;"
                     :: "l"(&g_rows[f]), "r"((unsigned int)q) : "memory");
        unsigned int v;
        asm volatile("atom.acq_rel.gpu.global.add.u32 %0, [%1], %2;"
                     : "=r"(v) : "l"(&g_done), "r"(1u) : "memory");
        s_last = (v == NF - 1) ? 1 : 0;
    }
    __syncthreads();

    // ---- Last block computes the mode over g_rows ----
    if (s_last) {
        __shared__ int cnt[NQ];
        #pragma unroll
        for (int i = 0; i < NQ / TPB; i++) cnt[i * TPB + tid] = 0;
        __syncthreads();

        // one g_rows entry per thread (NF == TPB)
        unsigned int r;
        asm volatile("ld.relaxed.gpu.global.u32 %0, [%1];"
                     : "=r"(r) : "l"(&g_rows[tid]) : "memory");
        atomicAdd(&cnt[r], 1);
        __syncthreads();

        // key = (count << 10) | (1023 - idx): max => max count, then min idx
        int mykey = 0;
        #pragma unroll
        for (int i = 0; i < NQ / TPB; i++) {
            const int bin = i * TPB + tid;
            const int k = (cnt[bin] << 10) | (NQ - 1 - bin);
            if (k > mykey) mykey = k;
        }
        const int wmax = (int)__reduce_max_sync(0xFFFFFFFFu, (unsigned int)mykey);

        __shared__ int warp_max[TPB / 32];
        if (lane == 0) warp_max[wid] = wmax;
        __syncthreads();
        if (tid == 0) {
            int m = warp_max[0];
            #pragma unroll
            for (int w = 1; w < TPB / 32; w++)
                if (warp_max[w] > m) m = warp_max[w];
            const int mode_idx = (NQ - 1) - (m & (NQ - 1));
            out[C_SIZE + NF] = (float)mode_idx;
            g_done = 0;   // reset for next graph replay
        }
    }
}

extern "C" void kernel_launch(void* const* d_in, const int* in_sizes, int n_in,
                              void* d_out, int out_size)
{
    // metadata order: pred_logits, pred_logits_b, pred_boxes, tgt_bbox, tgt_ids
    const float* logits_b = (const float*)d_in[1];
    const float* boxes    = (const float*)d_in[2];
    const float* tgt      = (const float*)d_in[3];
    float* out = (float*)d_out;

    fused_kernel<<<NF, TPB>>>(logits_b, boxes, tgt, out);
}

// round 4
// speedup vs baseline: 1.2381x; 1.0208x over previous
#include <cuda_runtime.h>
#include <cuda_bf16.h>

// Shapes: pred_logits [16,32,1024,80] (UNUSED), pred_logits_b [16,32,1024,2],
//         pred_boxes [16,32,1024,4], tgt_bbox [16,32,1,4], tgt_ids [512] (UNUSED)
// Output (f32, concatenated): C [512*1024], rows [512], mode_idx [1]

#define NQ  1024
#define NF  512
#define C_SIZE (NF * NQ)
#define TPB 256               // threads per block; 4 consecutive queries per thread

__device__ __align__(16) int g_cnt[NQ];   // zero-init; bincount of selected rows
__device__ unsigned int      g_done;      // zero-init completion counter

// Monotone float -> uint mapping: a < b  <=>  enc(a) < enc(b)
__device__ __forceinline__ unsigned int float_to_ordered(float f) {
    unsigned int u = __float_as_uint(f);
    return (u & 0x80000000u) ? ~u : (u | 0x80000000u);
}

__global__ void __launch_bounds__(TPB, 4)
fused_kernel(const float* __restrict__ logits_b,
             const float* __restrict__ boxes,
             const float* __restrict__ tgt,
             float* __restrict__ out)
{
    const int f    = blockIdx.x;   // frame 0..511
    const int tid  = threadIdx.x;  // 0..255
    const int lane = tid & 31;
    const int wid  = tid >> 5;     // 0..7

    // Target box (cxcywh -> xyxy)
    const float4 tb = reinterpret_cast<const float4*>(tgt)[f];
    const float tx1 = tb.x - 0.5f * tb.z;
    const float ty1 = tb.y - 0.5f * tb.w;
    const float tx2 = tb.x + 0.5f * tb.z;
    const float ty2 = tb.y + 0.5f * tb.w;
    const float area2 = (tx2 - tx1) * (ty2 - ty1);

    const float4* __restrict__ bptr = reinterpret_cast<const float4*>(boxes)    + (size_t)f * NQ;
    const float4* __restrict__ lptr = reinterpret_cast<const float4*>(logits_b) + (size_t)f * (NQ / 2);
    float4* __restrict__ cptr = reinterpret_cast<float4*>(out + (size_t)f * NQ);

    // Thread t handles queries q0 = 4t .. 4t+3 (consecutive):
    //   boxes:  2 float4 loads; logits: 2 float4 loads (2 q per float4)
    const int q0 = tid * 4;
    float4 p[4];
    p[0] = bptr[q0 + 0];
    p[1] = bptr[q0 + 1];
    p[2] = bptr[q0 + 2];
    p[3] = bptr[q0 + 3];
    const float4 la = lptr[tid * 2 + 0];   // (l0.x,l0.y,l1.x,l1.y)
    const float4 lb = lptr[tid * 2 + 1];   // (l2.x,l2.y,l3.x,l3.y)

    const float ld_[4][2] = { {la.x, la.y}, {la.z, la.w}, {lb.x, lb.y}, {lb.z, lb.w} };

    float cres[4];
    unsigned int obest = 0xFFFFFFFFu;
    int          bestq = 0;

    #pragma unroll
    for (int i = 0; i < 4; i++) {
        const int q = q0 + i;

        const float cost_bbox = fabsf(p[i].x - tb.x) + fabsf(p[i].y - tb.y)
                              + fabsf(p[i].z - tb.z) + fabsf(p[i].w - tb.w);

        const float x1 = p[i].x - 0.5f * p[i].z;
        const float y1 = p[i].y - 0.5f * p[i].w;
        const float x2 = p[i].x + 0.5f * p[i].z;
        const float y2 = p[i].y + 0.5f * p[i].w;
        const float area1 = (x2 - x1) * (y2 - y1);

        const float lt_x = fmaxf(x1, tx1), lt_y = fmaxf(y1, ty1);
        const float rb_x = fminf(x2, tx2), rb_y = fminf(y2, ty2);
        const float iw = fmaxf(rb_x - lt_x, 0.0f);
        const float ih = fmaxf(rb_y - lt_y, 0.0f);
        const float inter = iw * ih;
        const float uni   = area1 + area2 - inter;
        const float iou   = inter / uni;

        const float cx1 = fminf(x1, tx1), cy1 = fminf(y1, ty1);
        const float cx2 = fmaxf(x2, tx2), cy2 = fmaxf(y2, ty2);
        const float cw = fmaxf(cx2 - cx1, 0.0f);
        const float ch = fmaxf(cy2 - cy1, 0.0f);
        const float areac = cw * ch;
        const float giou  = iou - (areac - uni) / areac;

        const float cost_class = -1.0f / (1.0f + expf(ld_[i][0] - ld_[i][1]));

        const float c = 5.0f * cost_bbox + cost_class - 2.0f * giou;
        cres[i] = c;

        const unsigned int oc = float_to_ordered(c);
        if (oc < obest) { obest = oc; bestq = q; }   // q increasing -> first-min kept
    }

    cptr[tid] = make_float4(cres[0], cres[1], cres[2], cres[3]);

    // Warp argmin: min cost, then min q among cost-ties (exact JAX tie-break)
    const unsigned int wmin = __reduce_min_sync(0xFFFFFFFFu, obest);
    const unsigned int qc   = (obest == wmin) ? (unsigned int)bestq : 0xFFFFFFFFu;
    const unsigned int wq   = __reduce_min_sync(0xFFFFFFFFu, qc);

    __shared__ unsigned long long warp_min[TPB / 32];
    __shared__ int s_last;
    if (lane == 0)
        warp_min[wid] = ((unsigned long long)wmin << 32) | wq;
    __syncthreads();

    if (tid == 0) {
        unsigned long long m = warp_min[0];
        #pragma unroll
        for (int w = 1; w < TPB / 32; w++)
            if (warp_min[w] < m) m = warp_min[w];
        const int q = (int)(m & 0xFFFFFFFFu);
        out[C_SIZE + f] = (float)q;      // rows output

        // Bincount contribution now (overlaps other CTAs' work), then
        // release-increment the completion counter.
        atomicAdd(&g_cnt[q], 1);         // relaxed gpu-scope RMW in L2
        unsigned int v;
        asm volatile("atom.acq_rel.gpu.global.add.u32 %0, [%1], %2;"
                     : "=r"(v) : "l"(&g_done), "r"(1u) : "memory");
        s_last = (v == NF - 1) ? 1 : 0;
    }
    __syncthreads();

    // ---- Last block: argmax over g_cnt with smallest-index tie-break ----
    if (s_last) {
        int mykey = 0;
        int cvals[4];
        #pragma unroll
        for (int i = 0; i < 4; i++) {
            const int bin = tid * 4 + i;
            int c;
            asm volatile("ld.relaxed.gpu.global.s32 %0, [%1];"
                         : "=r"(c) : "l"(&g_cnt[bin]) : "memory");
            cvals[i] = c;
            const int k = (c << 10) | (NQ - 1 - bin);
            if (k > mykey) mykey = k;
        }
        // reset g_cnt for the next graph replay
        #pragma unroll
        for (int i = 0; i < 4; i++) {
            asm volatile("st.relaxed.gpu.global.s32 [%0], %1;"
                         :: "l"(&g_cnt[tid * 4 + i]), "r"(0) : "memory");
        }
        (void)cvals;

        const int wmax = (int)__reduce_max_sync(0xFFFFFFFFu, (unsigned int)mykey);
        __shared__ int warp_max[TPB / 32];
        if (lane == 0) warp_max[wid] = wmax;
        __syncthreads();
        if (tid == 0) {
            int m = warp_max[0];
            #pragma unroll
            for (int w = 1; w < TPB / 32; w++)
                if (warp_max[w] > m) m = warp_max[w];
            const int mode_idx = (NQ - 1) - (m & (NQ - 1));
            out[C_SIZE + NF] = (float)mode_idx;
            g_done = 0;   // reset for next replay
        }
    }
}

extern "C" void kernel_launch(void* const* d_in, const int* in_sizes, int n_in,
                              void* d_out, int out_size)
{
    // metadata order: pred_logits, pred_logits_b, pred_boxes, tgt_bbox, tgt_ids
    const float* logits_b = (const float*)d_in[1];
    const float* boxes    = (const float*)d_in[2];
    const float* tgt      = (const float*)d_in[3];
    float* out = (float*)d_out;

    fused_kernel<<<NF, TPB>>>(logits_b, boxes, tgt, out);
}